// round 2
// baseline (speedup 1.0000x reference)
#include <cuda_runtime.h>

#define NDIMS  3
#define NCOLS  500000
#define RANKV  64
#define K1V    32
#define BATCHV 8192
#define NGATH  (NDIMS * BATCHV * RANKV)   /* 1,572,864 gathered KL elements */

__device__ double g_exp_sum;
__device__ double g_kl_sum;

// ---------------------------------------------------------------------------
// Fast natural log (Cephes logf polynomial, FMA-pipe only). x > 0.
// ---------------------------------------------------------------------------
__device__ __forceinline__ float fast_ln(float x) {
    int   i = __float_as_int(x);
    int   e = (i - 0x3F3504F3) >> 23;
    float m = __int_as_float(i - (e << 23));          // m in [0.7071, 1.4142)
    float z = m - 1.0f;
    float p =            7.0376836292e-2f;
    p = fmaf(p, z, -1.1514610310e-1f);
    p = fmaf(p, z,  1.1676998740e-1f);
    p = fmaf(p, z, -1.2420140846e-1f);
    p = fmaf(p, z,  1.4249322787e-1f);
    p = fmaf(p, z, -1.6668057665e-1f);
    p = fmaf(p, z,  2.0000714765e-1f);
    p = fmaf(p, z, -2.4999993993e-1f);
    p = fmaf(p, z,  3.3333331174e-1f);
    float z2 = z * z;
    float y  = p * z2 * z;
    y = fmaf(-0.5f, z2, y);
    return fmaf((float)e, 0.693147180559945f, z + y);
}

__global__ void init_k() { g_exp_sum = 0.0; g_kl_sum = 0.0; }

// ---------------------------------------------------------------------------
// Fused kernel: one block per batch element.
//  - gather m/L rows (each thread: rank slice {2*lane, 2*lane+1}, all 3 dims)
//  - warp w handles MC samples k = w, w+8, ... (expectation term)
//  - warp 0 additionally computes the KL over the gathered values
// ---------------------------------------------------------------------------
__global__ void fused_k(const int*   __restrict__ entries,
                        const float* __restrict__ ys,
                        const float* __restrict__ means,
                        const float* __restrict__ chols,
                        const float* __restrict__ eps) {
    int b = blockIdx.x;
    int t = threadIdx.x;
    int w = t >> 5, lane = t & 31;

    int r0 = entries[b * 3 + 0];
    int r1 = entries[b * 3 + 1];
    int r2 = entries[b * 3 + 2];

    const float2* M = (const float2*)means;
    const float2* C = (const float2*)chols;
    long i0 = ((long)0 * NCOLS + r0) * 32 + lane;
    long i1 = ((long)1 * NCOLS + r1) * 32 + lane;
    long i2 = ((long)2 * NCOLS + r2) * 32 + lane;
    float2 m0 = __ldg(M + i0), m1 = __ldg(M + i1), m2 = __ldg(M + i2);
    float2 c0 = __ldg(C + i0), c1 = __ldg(C + i1), c2 = __ldg(C + i2);
    // S = L^2 (the reparameterization scale)
    float l0x = c0.x * c0.x, l0y = c0.y * c0.y;
    float l1x = c1.x * c1.x, l1y = c1.y * c1.y;
    float l2x = c2.x * c2.x, l2y = c2.y * c2.y;

    float y = __ldg(ys + b);

    const float2* E = (const float2*)eps;
    const long dstride = (long)BATCHV * K1V * 32;
    const long base    = (long)b * K1V * 32 + lane;

    float lp = 0.f;
    #pragma unroll
    for (int k = w; k < K1V; k += 8) {
        long off = base + (long)k * 32;
        float2 eA = __ldg(E + off);
        float2 eB = __ldg(E + off + dstride);
        float2 eC = __ldg(E + off + 2 * dstride);
        float tx = fmaf(eA.x, l0x, m0.x) * fmaf(eB.x, l1x, m1.x) * fmaf(eC.x, l2x, m2.x);
        float ty = fmaf(eA.y, l0y, m0.y) * fmaf(eB.y, l1y, m1.y) * fmaf(eC.y, l2y, m2.y);
        float s = tx + ty;
        #pragma unroll
        for (int o = 16; o; o >>= 1) s += __shfl_xor_sync(0xffffffffu, s, o);
        float d = s - y;
        lp = fmaf(-0.5f * d, d, lp);        // -0.5*(fs - y)^2
    }

    // KL over gathered values: only warp 0 (all warps hold identical copies).
    // kl = 0.5*(S^2 + m^2 - 1 - log(S^2)),  S = L^2  =>  log(S^2) = 4*ln|L|
    // Accumulate 0.5*(S^2 + m^2) - 2*ln|L|; the "-0.5" constant folds into fin.
    float klp = 0.f;
    if (w == 0) {
        klp  = 0.5f * (fmaf(l0x, l0x, m0.x * m0.x) + fmaf(l0y, l0y, m0.y * m0.y)
                     + fmaf(l1x, l1x, m1.x * m1.x) + fmaf(l1y, l1y, m1.y * m1.y)
                     + fmaf(l2x, l2x, m2.x * m2.x) + fmaf(l2y, l2y, m2.y * m2.y));
        klp -= 2.0f * (fast_ln(fabsf(c0.x)) + fast_ln(fabsf(c0.y))
                     + fast_ln(fabsf(c1.x)) + fast_ln(fabsf(c1.y))
                     + fast_ln(fabsf(c2.x)) + fast_ln(fabsf(c2.y)));
        #pragma unroll
        for (int o = 16; o; o >>= 1) klp += __shfl_xor_sync(0xffffffffu, klp, o);
    }

    __shared__ float wlp[8];
    if (lane == 0) wlp[w] = lp;
    __syncthreads();
    if (t == 0) {
        float s = wlp[0] + wlp[1] + wlp[2] + wlp[3]
                + wlp[4] + wlp[5] + wlp[6] + wlp[7];
        s -= (float)K1V * 0.91893853320467274f;   // K1 * 0.5*ln(2*pi)
        atomicAdd(&g_exp_sum, (double)s);
        atomicAdd(&g_kl_sum, (double)klp);
    }
}

__global__ void fin_k(float* out) {
    double E     = g_exp_sum / (double)K1V;            // mean over K1, sum over B
    double klsum = g_kl_sum - 0.5 * (double)NGATH;     // restore the "-1" per elem
    // loss = -(NUM_TRAIN/B * E + batch_kl/B),  batch_kl = -klsum
    out[0] = (float)(-(100.0 * E - klsum / (double)BATCHV));
}

extern "C" void kernel_launch(void* const* d_in, const int* in_sizes, int n_in,
                              void* d_out, int out_size) {
    const int*   entries = (const int*)  d_in[0];
    const float* ys      = (const float*)d_in[1];
    const float* means   = (const float*)d_in[2];
    const float* chols   = (const float*)d_in[3];
    const float* eps     = (const float*)d_in[4];

    init_k<<<1, 1>>>();
    fused_k<<<BATCHV, 256>>>(entries, ys, means, chols, eps);
    fin_k<<<1, 1>>>((float*)d_out);
}